// round 13
// baseline (speedup 1.0000x reference)
#include <cuda_runtime.h>
#include <cuda_fp16.h>
#include <math.h>
#include <stdint.h>

#define Lq 12
#define Eq 1024
#define Hq 16
#define Tq 512
#define Bq 8
#define Vq 512
#define Fq 4096
#define Dq 64
#define Mq (Bq*Tq)
#define E3 (3*Eq)

// ---------------- scratch ----------------------------------------------------
__device__ float g_h[Mq*Eq];
__device__ float g_bqkv[Lq*E3];
__device__ __half g_xn_hi[Mq*Eq],  g_xn_lo[Mq*Eq];
__device__ __half g_qkv_hi[(size_t)Mq*E3], g_qkv_lo[(size_t)Mq*E3];
__device__ __half g_y_hi [Mq*Eq],  g_y_lo [Mq*Eq];
__device__ __half g_ml_hi[(size_t)Mq*Fq], g_ml_lo[(size_t)Mq*Fq];
__device__ __half g_wqkv[(size_t)Lq*E3*Eq];
__device__ __half g_wp[(size_t)Lq*Eq*Eq];
__device__ __half g_w1[(size_t)Lq*Eq*Fq];
__device__ __half g_w2[(size_t)Lq*Fq*Eq];
__device__ __half g_wh[(size_t)Eq*Vq];

// ---------------- helpers ----------------------------------------------------
__device__ __forceinline__ uint32_t smem_u32(const void* p) {
    uint32_t a;
    asm("{ .reg .u64 t; cvta.to.shared.u64 t, %1; cvt.u32.u64 %0, t; }" : "=r"(a) : "l"(p));
    return a;
}
#define SW128(o) ((o) ^ (((o) >> 3) & 0x70))
#define CP16(dst, src) \
    asm volatile("cp.async.cg.shared.global [%0], [%1], 16;" :: "r"(dst), "l"(src) : "memory")
#define CP_COMMIT() asm volatile("cp.async.commit_group;" ::: "memory")
#define CP_WAIT1()  asm volatile("cp.async.wait_group 1;" ::: "memory")
#define CP_WAIT0()  asm volatile("cp.async.wait_group 0;" ::: "memory")
#define LDSM4(r0, r1, r2, r3, addr) \
    asm volatile("ldmatrix.sync.aligned.m8n8.x4.shared.b16 {%0,%1,%2,%3}, [%4];" \
                 : "=r"(r0), "=r"(r1), "=r"(r2), "=r"(r3) : "r"(addr))
#define LDSM4T(r0, r1, r2, r3, addr) \
    asm volatile("ldmatrix.sync.aligned.m8n8.x4.trans.shared.b16 {%0,%1,%2,%3}, [%4];" \
                 : "=r"(r0), "=r"(r1), "=r"(r2), "=r"(r3) : "r"(addr))
#define MMA_F16(c, a, b) \
    asm volatile("mma.sync.aligned.m16n8k16.row.col.f32.f16.f16.f32 " \
                 "{%0,%1,%2,%3}, {%4,%5,%6,%7}, {%8,%9}, {%0,%1,%2,%3};" \
                 : "+f"((c)[0]), "+f"((c)[1]), "+f"((c)[2]), "+f"((c)[3]) \
                 : "r"((a)[0]), "r"((a)[1]), "r"((a)[2]), "r"((a)[3]), \
                   "r"((b)[0]), "r"((b)[1]))
#define MMA_F16B(c, a, b0, b1) \
    asm volatile("mma.sync.aligned.m16n8k16.row.col.f32.f16.f16.f32 " \
                 "{%0,%1,%2,%3}, {%4,%5,%6,%7}, {%8,%9}, {%0,%1,%2,%3};" \
                 : "+f"((c)[0]), "+f"((c)[1]), "+f"((c)[2]), "+f"((c)[3]) \
                 : "r"((a)[0]), "r"((a)[1]), "r"((a)[2]), "r"((a)[3]), \
                   "r"(b0), "r"(b1))

__device__ __forceinline__ void split2h(float x, float y, uint32_t& h, uint32_t& l) {
    asm("cvt.rn.f16x2.f32 %0, %1, %2;" : "=r"(h) : "f"(y), "f"(x));
    __half2 hh = *reinterpret_cast<__half2*>(&h);
    float hx = __low2float(hh), hy = __high2float(hh);
    asm("cvt.rn.f16x2.f32 %0, %1, %2;" : "=r"(l) : "f"(y - hy), "f"(x - hx));
}

// ---------------- merged weight conversion + bias packing --------------------
__global__ __launch_bounds__(256)
void convAll(const float* __restrict__ Wq, const float* __restrict__ Wk,
             const float* __restrict__ Wv, const float* __restrict__ Wp,
             const float* __restrict__ W1, const float* __restrict__ W2,
             const float* __restrict__ Wh,
             const float* __restrict__ bq, const float* __restrict__ bk,
             const float* __restrict__ bv,
             __half* oqkv, __half* op, __half* o1, __half* o2, __half* oh,
             float* obias)
{
    int b = blockIdx.x;
    int tid = threadIdx.x;
    if (b >= 147968) {
        int l = b - 147968;
        for (int i = tid; i < Eq; i += 256) {
            obias[l*E3 + i]          = bq[l*Eq + i];
            obias[l*E3 + Eq + i]     = bk[l*Eq + i];
            obias[l*E3 + 2*Eq + i]   = bv[l*Eq + i];
        }
        return;
    }
    const float* W; __half* O; int K, N; int rowoff = 0; size_t lstride;
    if (b < 49152) {
        int g = b / 12288; b -= g * 12288; K = Eq; N = Eq;
        if (g < 3) { W = (g==0) ? Wq : (g==1) ? Wk : Wv; O = oqkv; rowoff = g*Eq; lstride = (size_t)E3*Eq; }
        else       { W = Wp; O = op; lstride = (size_t)Eq*Eq; }
    } else if (b < 98304)  { b -= 49152; K = Eq; N = Fq; W = W1; O = o1; lstride = (size_t)Eq*Fq; }
    else if (b < 147456)   { b -= 98304; K = Fq; N = Eq; W = W2; O = o2; lstride = (size_t)Fq*Eq; }
    else                   { b -= 147456; K = Eq; N = Vq; W = Wh; O = oh; lstride = (size_t)Eq*Vq; }
    int tilesN = N >> 5;
    int per = tilesN * (K >> 5);
    int l = b / per; int rem = b - l * per;
    int kt = rem / tilesN, nt = rem - kt * tilesN;
    const float* Wl = W + (size_t)l * K * N;
    __half* Ol = O + (size_t)l * lstride;
    int k0 = kt * 32, n0 = nt * 32;
    __shared__ float t[32][33];
    int r = tid >> 5, c = tid & 31;
    #pragma unroll
    for (int i = 0; i < 4; i++)
        t[r + 8*i][c] = Wl[(size_t)(k0 + r + 8*i) * N + n0 + c];
    __syncthreads();
    #pragma unroll
    for (int i = 0; i < 4; i++)
        Ol[(size_t)(rowoff + n0 + r + 8*i) * K + k0 + c] = __float2half(t[c][r + 8*i]);
}

// ---------------- embedding ---------------------------------------------------
__global__ void embed_kernel(const int* __restrict__ x,
                             const float* __restrict__ tok,
                             const float* __restrict__ pos,
                             float* __restrict__ out)
{
    int row = blockIdx.x;
    int t   = row & (Tq-1);
    int id  = x[row];
    int tid = threadIdx.x;
    float4 a = ((const float4*)(tok + (size_t)id*Eq))[tid];
    float4 p = ((const float4*)(pos + (size_t)t*Eq))[tid];
    float4 o; o.x=a.x+p.x; o.y=a.y+p.y; o.z=a.z+p.z; o.w=a.w+p.w;
    ((float4*)(out + (size_t)row*Eq))[tid] = o;
}

// ---------------- layernorm ---------------------------------------------------
__global__ void ln_kernel(const float* __restrict__ x,
                          const float* __restrict__ g,
                          const float* __restrict__ b,
                          __half* __restrict__ ohi,
                          __half* __restrict__ olo)
{
    int row = blockIdx.x;
    int tid = threadIdx.x;
    const float4* xr = (const float4*)(x + (size_t)row*Eq);
    float4 xv = xr[tid];
    float s  = xv.x + xv.y + xv.z + xv.w;
    float sq = xv.x*xv.x + xv.y*xv.y + xv.z*xv.z + xv.w*xv.w;
    #pragma unroll
    for (int off = 16; off > 0; off >>= 1) {
        s  += __shfl_xor_sync(0xffffffffu, s,  off);
        sq += __shfl_xor_sync(0xffffffffu, sq, off);
    }
    __shared__ float r1[8], r2[8];
    int w = tid >> 5;
    if ((tid & 31) == 0) { r1[w] = s; r2[w] = sq; }
    __syncthreads();
    float ts = 0.f, tq = 0.f;
    #pragma unroll
    for (int i = 0; i < 8; i++) { ts += r1[i]; tq += r2[i]; }
    float mean = ts * (1.0f/Eq);
    float var  = tq * (1.0f/Eq) - mean*mean;
    float rstd = rsqrtf(var + 1e-5f);
    float4 gv = ((const float4*)g)[tid];
    float4 bv = ((const float4*)b)[tid];
    float4 ov;
    ov.x = (xv.x-mean)*rstd*gv.x + bv.x;
    ov.y = (xv.y-mean)*rstd*gv.y + bv.y;
    ov.z = (xv.z-mean)*rstd*gv.z + bv.z;
    ov.w = (xv.w-mean)*rstd*gv.w + bv.w;
    uint32_t h0,h1,l0,l1;
    split2h(ov.x, ov.y, h0, l0);
    split2h(ov.z, ov.w, h1, l1);
    uint2 hv; hv.x = h0; hv.y = h1;
    uint2 lv; lv.x = l0; lv.y = l1;
    ((uint2*)(ohi + (size_t)row*Eq))[tid] = hv;
    ((uint2*)(olo + (size_t)row*Eq))[tid] = lv;
}

// ================ HMMA fp16 GEMM: 3-stage, fragment double-buffered ==========
// Stage = {Ah,Al,B} 48KB x 3 = 144KB (1 CTA/SM, no reg cap). One sync/chunk.
// Per-warp ks stagger + ldmatrix/MMA register pipelining inside each chunk.
#define ST_STRIDE 49152u
#define GT_SMEM (3*49152)

__device__ __forceinline__ float gelu_exact(float v) {
    return 0.5f * v * (1.0f + erff(v * 0.7071067811865475f));
}

__global__ __launch_bounds__(256)
void gemm_hf(const __half* __restrict__ Ah, const __half* __restrict__ Al,
             const __half* __restrict__ Bh,
             const float* __restrict__ bias, const float* __restrict__ res,
             float* __restrict__ C, __half* __restrict__ Chi,
             __half* __restrict__ Clo, int M, int N, int K, int act)
{
    extern __shared__ char smem[];
    const uint32_t sbase = smem_u32(smem);
    const int tid  = threadIdx.x;
    const int wid  = tid >> 5;
    const int lane = tid & 31;
    const int bm = blockIdx.y * 128;
    const int bn = blockIdx.x * 128;

    uint32_t soff[4];
    #pragma unroll
    for (int c = 0; c < 4; c++)
        soff[c] = SW128((uint32_t)((32*c + (tid >> 3))*128 + (tid & 7)*16));
    const size_t aBase0 = (size_t)(bm + (tid >> 3)) * K + (tid & 7)*8;
    const size_t bBase0 = (size_t)(bn + (tid >> 3)) * K + (tid & 7)*8;

    const int m0 = (wid & 3) * 32;
    const int n0 = (wid >> 2) * 64;
    uint32_t aRow[2], aMask[2];
    #pragma unroll
    for (int mt = 0; mt < 2; mt++) {
        int r = m0 + mt*16 + (lane & 15);
        aRow[mt]  = (uint32_t)r * 128u;
        aMask[mt] = (uint32_t)(r & 7) << 4;
    }
    const uint32_t kA = ((uint32_t)(lane >> 4)) << 4;
    uint32_t bRow[4], bMask[4];
    #pragma unroll
    for (int p = 0; p < 4; p++) {
        int r = n0 + p*16 + (((lane >> 4) & 1) << 3) + (lane & 7);
        bRow[p]  = (uint32_t)r * 128u;
        bMask[p] = (uint32_t)(r & 7) << 4;
    }
    const uint32_t kB = ((uint32_t)(lane & 8)) << 1;

    float acc[2][8][4];
    #pragma unroll
    for (int mt = 0; mt < 2; mt++)
        #pragma unroll
        for (int nt = 0; nt < 8; nt++)
            #pragma unroll
            for (int c = 0; c < 4; c++) acc[mt][nt][c] = 0.f;

    const int nst = K >> 6;
    const uint32_t st = (uint32_t)(wid & 3);   // per-warp ks stagger

    auto load_stage = [&](uint32_t sb, int s) {
        const __half* Asrc_h = Ah + aBase0 + (size_t)s*64;
        const __half* Asrc_l = Al + aBase0 + (size_t)s*64;
        const __half* Bsrc   = Bh + bBase0 + (size_t)s*64;
        #pragma unroll
        for (int c = 0; c < 4; c++) {
            size_t o = (size_t)(32*c) * K;
            CP16(sb + soff[c],          Asrc_h + o);
            CP16(sb + 16384u + soff[c], Asrc_l + o);
            CP16(sb + 32768u + soff[c], Bsrc + o);
        }
        CP_COMMIT();
    };

    load_stage(sbase, 0);
    if (nst > 1) load_stage(sbase + ST_STRIDE, 1);

    int buf = 0;
    for (int s = 0; s < nst; s++) {
        if (s + 1 < nst) CP_WAIT1(); else CP_WAIT0();
        __syncthreads();
        if (s + 2 < nst) {
            int nb = buf + 2; if (nb >= 3) nb -= 3;
            load_stage(sbase + (uint32_t)nb * ST_STRIDE, s + 2);
        }
        {
            const uint32_t tb = sbase + (uint32_t)buf * ST_STRIDE;
            const uint32_t bufAh = tb, bufAl = tb + 16384u, bufB = tb + 32768u;

            // fragment double buffers: [parity][...]
            uint32_t aF[2][2][2][4];   // [buf][term][mt][4]
            uint32_t bF[2][8][2];      // [buf][nt][2]

            // load fragments for iteration it into parity p
            #define LDFRAG(it_, p_) do { \
                uint32_t co_ = (((uint32_t)(it_) + st) & 3u) * 32u; \
                _Pragma("unroll") \
                for (int mt = 0; mt < 2; mt++) { \
                    uint32_t off_ = aRow[mt] + ((co_ + kA) ^ aMask[mt]); \
                    LDSM4(aF[p_][0][mt][0], aF[p_][0][mt][1], aF[p_][0][mt][2], aF[p_][0][mt][3], bufAh + off_); \
                    LDSM4(aF[p_][1][mt][0], aF[p_][1][mt][1], aF[p_][1][mt][2], aF[p_][1][mt][3], bufAl + off_); \
                } \
                _Pragma("unroll") \
                for (int p = 0; p < 4; p++) { \
                    uint32_t off_ = bRow[p] + ((co_ + kB) ^ bMask[p]); \
                    uint32_t t0_,t1_,t2_,t3_; \
                    LDSM4(t0_, t1_, t2_, t3_, bufB + off_); \
                    bF[p_][2*p][0]=t0_; bF[p_][2*p][1]=t1_; \
                    bF[p_][2*p+1][0]=t2_; bF[p_][2*p+1][1]=t3_; \
                } \
            } while (0)

            LDFRAG(0, 0);
            #pragma unroll
            for (int it = 0; it < 4; it++) {
                const int cb = it & 1;
                if (it < 3) {
                    if (cb == 0) LDFRAG(it + 1, 1);
                    else         LDFRAG(it + 1, 0);
                }
                #pragma unroll
                for (int mt = 0; mt < 2; mt++)
                    #pragma unroll
                    for (int nt = 0; nt < 8; nt++) {
                        MMA_F16(acc[mt][nt], aF[cb][0][mt], bF[cb][nt]);
                        MMA_F16(acc[mt][nt], aF[cb][1][mt], bF[cb][nt]);
                    }
            }
            #undef LDFRAG
        }
        buf++; if (buf >= 3) buf -= 3;
    }

    // ---- epilogue ----
    #pragma unroll
    for (int mt = 0; mt < 2; mt++) {
        #pragma unroll
        for (int nt = 0; nt < 8; nt++) {
            int mrow = bm + m0 + mt*16 + (lane >> 2);
            int ncol = bn + n0 + nt*8 + ((lane & 3) << 1);
            #pragma unroll
            for (int half = 0; half < 2; half++) {
                int m = mrow + half*8;
                float v0 = acc[mt][nt][half*2 + 0];
                float v1 = acc[mt][nt][half*2 + 1];
                if (bias) { v0 += bias[ncol]; v1 += bias[ncol + 1]; }
                if (act)  { v0 = gelu_exact(v0); v1 = gelu_exact(v1); }
                if (res) {
                    const float2 rr = *(const float2*)(res + (size_t)m * N + ncol);
                    v0 += rr.x; v1 += rr.y;
                }
                if (C) {
                    float2 o; o.x = v0; o.y = v1;
                    *(float2*)(C + (size_t)m * N + ncol) = o;
                }
                if (Chi) {
                    uint32_t hh, ll;
                    split2h(v0, v1, hh, ll);
                    *(uint32_t*)(Chi + (size_t)m * N + ncol) = hh;
                    *(uint32_t*)(Clo + (size_t)m * N + ncol) = ll;
                }
            }
        }
    }
}

// ================ fused flash attention (packed QKV input) ==================
#define FA_SMEM 65536

__global__ __launch_bounds__(128)
void attn_fused(const __half* __restrict__ qkvh, const __half* __restrict__ qkvl,
                __half* __restrict__ yhi, __half* __restrict__ ylo)
{
    const int qt = blockIdx.x & 7;
    const int bh = blockIdx.x >> 3;
    const int hh = bh & (Hq-1);
    const int bb = bh >> 4;
    const int q0 = qt * 64;
    const int tid = threadIdx.x, lane = tid & 31, w = tid >> 5;

    extern __shared__ char smem[];
    const uint32_t sb = smem_u32(smem);
    const uint32_t sQh = sb, sQl = sb + 8192u;

    const int lr = tid >> 1, lc = tid & 1;
    uint32_t ldst[4];
    #pragma unroll
    for (int i = 0; i < 4; i++)
        ldst[i] = SW128((uint32_t)(lr*128 + lc*64 + i*16));
    const size_t coloff = (size_t)hh*64 + lc*32;

    {   // Q tile
        size_t rb = ((size_t)(bb*Tq + q0 + lr))*E3 + coloff;
        #pragma unroll
        for (int i = 0; i < 4; i++) CP16(sQh + ldst[i], qkvh + rb + i*8);
        #pragma unroll
        for (int i = 0; i < 4; i++) CP16(sQl + ldst[i], qkvl + rb + i*8);
        CP_COMMIT();
    }
    {   // KV tile 0
        size_t rb = ((size_t)(bb*Tq + lr))*E3 + coloff;
        uint32_t kvb = sb + 16384u;
        #pragma unroll
        for (int i = 0; i < 4; i++) CP16(kvb + ldst[i],          qkvh + rb + Eq   + i*8);
        #pragma unroll
        for (int i = 0; i < 4; i++) CP16(kvb + 8192u + ldst[i],  qkvh + rb + 2*Eq + i*8);
        #pragma unroll
        for (int i = 0; i < 4; i++) CP16(kvb + 16384u + ldst[i], qkvl + rb + 2*Eq + i*8);
        CP_COMMIT();
    }

    const int arow = w*16 + (lane & 15);
    const uint32_t aRow = (uint32_t)arow * 128u;
    const uint32_t aMask = (uint32_t)(arow & 7) << 4;
    const uint32_t kA = ((uint32_t)(lane >> 4)) << 4;
    uint32_t bRow[4], bMask[4];
    #pragma unroll
    for (int p = 0; p < 4; p++) {
        int r = p*16 + (((lane >> 4) & 1) << 3) + (lane & 7);
        bRow[p]  = (uint32_t)r * 128u;
        bMask[p] = (uint32_t)(r & 7) << 4;
    }
    const uint32_t kB = ((uint32_t)(lane & 8)) << 1;
    const int vsub = lane >> 3, vrow = lane & 7;
    const int vtok = ((vsub & 1) << 3) + vrow;
    const int vd   = (vsub >> 1) << 3;

    float o[8][4];
    #pragma unroll
    for (int nf = 0; nf < 8; nf++)
        #pragma unroll
        for (int e = 0; e < 4; e++) o[nf][e] = 0.f;
    float m0r = -1e30f, m1r = -1e30f, l0r = 0.f, l1r = 0.f;

    const int nkt = qt + 1;
    for (int kt = 0; kt < nkt; kt++) {
        CP_WAIT0();
        __syncthreads();
        if (kt + 1 < nkt) {
            size_t rb = ((size_t)(bb*Tq + (kt+1)*64 + lr))*E3 + coloff;
            uint32_t kvb = sb + 16384u + (uint32_t)((kt+1) & 1)*24576u;
            #pragma unroll
            for (int i = 0; i < 4; i++) CP16(kvb + ldst[i],          qkvh + rb + Eq   + i*8);
            #pragma unroll
            for (int i = 0; i < 4; i++) CP16(kvb + 8192u + ldst[i],  qkvh + rb + 2*Eq + i*8);
            #pragma unroll
            for (int i = 0; i < 4; i++) CP16(kvb + 16384u + ldst[i], qkvl + rb + 2*Eq + i*8);
            CP_COMMIT();
        }
        const uint32_t kvb = sb + 16384u + (uint32_t)(kt & 1)*24576u;
        const uint32_t sK = kvb, sVh = kvb + 8192u, sVl = kvb + 16384u;

        float s[8][4];
        #pragma unroll
        for (int nf = 0; nf < 8; nf++)
            #pragma unroll
            for (int e = 0; e < 4; e++) s[nf][e] = 0.f;
        #pragma unroll
        for (int ks = 0; ks < 4; ks++) {
            uint32_t co = (uint32_t)(ks*32);
            uint32_t aoff = aRow + ((co + kA) ^ aMask);
            uint32_t ahr[4], alr[4];
            LDSM4(ahr[0], ahr[1], ahr[2], ahr[3], sQh + aoff);
            LDSM4(alr[0], alr[1], alr[2], alr[3], sQl + aoff);
            uint32_t bk[8][2];
            #pragma unroll
            for (int p = 0; p < 4; p++) {
                uint32_t off = bRow[p] + ((co + kB) ^ bMask[p]);
                uint32_t t0,t1,t2,t3;
                LDSM4(t0, t1, t2, t3, sK + off);
                bk[2*p][0]=t0; bk[2*p][1]=t1; bk[2*p+1][0]=t2; bk[2*p+1][1]=t3;
            }
            #pragma unroll
            for (int nf = 0; nf < 8; nf++) {
                MMA_F16(s[nf], ahr, bk[nf]);
                MMA_F16(s[nf], alr, bk[nf]);
            }
        }
        #pragma unroll
        for (int nf = 0; nf < 8; nf++)
            #pragma unroll
            for (int e = 0; e < 4; e++) s[nf][e] *= 0.125f;
        if (kt == qt) {
            int r0l = w*16 + (lane >> 2);
            #pragma unroll
            for (int nf = 0; nf < 8; nf++) {
                int col = nf*8 + ((lane & 3) << 1);
                if (col     > r0l)     s[nf][0] = -1e30f;
                if (col + 1 > r0l)     s[nf][1] = -1e30f;
                if (col     > r0l + 8) s[nf][2] = -1e30f;
                if (col + 1 > r0l + 8) s[nf][3] = -1e30f;
            }
        }
        float mx0 = -1e30f, mx1 = -1e30f;
        #pragma unroll
        for (int nf = 0; nf < 8; nf++) {
            mx0 = fmaxf(mx0, fmaxf(s[nf][0], s[nf][1]));
            mx1 = fmaxf(mx1, fmaxf(s[nf][2], s[nf][3]));
        }
        mx0 = fmaxf(mx0, __shfl_xor_sync(0xffffffffu, mx0, 1));
        mx0 = fmaxf(mx0, __shfl_xor_sync(0xffffffffu, mx0, 2));
        mx1 = fmaxf(mx1, __shfl_xor_sync(0xffffffffu, mx1, 1));
        mx1 = fmaxf(mx1, __shfl_xor_sync(0xffffffffu, mx1, 2));
        float mn0 = fmaxf(m0r, mx0), mn1 = fmaxf(m1r, mx1);
        float f0 = __expf(m0r - mn0), f1 = __expf(m1r - mn1);
        m0r = mn0; m1r = mn1;
        float ps0 = 0.f, ps1 = 0.f;
        #pragma unroll
        for (int nf = 0; nf < 8; nf++) {
            s[nf][0] = __expf(s[nf][0] - mn0); ps0 += s[nf][0];
            s[nf][1] = __expf(s[nf][1] - mn0); ps0 += s[nf][1];
            s[nf][2] = __expf(s[nf][2] - mn1); ps1 += s[nf][2];
            s[nf][3] = __expf(s[nf][3] - mn1); ps1 += s[nf][3];
        }
        ps0 += __shfl_xor_sync(0xffffffffu, ps0, 1);
        ps0 += __shfl_xor_sync(0xffffffffu, ps0, 2);
        ps1 += __shfl_xor_sync(0xffffffffu, ps1, 1);
        ps1 += __shfl_xor_sync(0xffffffffu, ps1, 2);
        l0r = l0r*f0 + ps0;
        l1r = l1r*f1 + ps1;
        #pragma unroll
        for (int nf = 0; nf < 8; nf++) {
            o[nf][0] *= f0; o[nf][1] *= f0;
            o[nf][2] *= f1; o[nf][3] *= f1;
        }
        #pragma unroll
        for (int kf = 0; kf < 4; kf++) {
            uint32_t ph[4], pl[4];
            split2h(s[2*kf][0],   s[2*kf][1],   ph[0], pl[0]);
            split2h(s[2*kf][2],   s[2*kf][3],   ph[1], pl[1]);
            split2h(s[2*kf+1][0], s[2*kf+1][1], ph[2], pl[2]);
            split2h(s[2*kf+1][2], s[2*kf+1][3], ph[3], pl[3]);
            int tok = kf*16 + vtok;
            uint32_t vrowoff = (uint32_t)tok * 128u;
            uint32_t vmask   = (uint32_t)(tok & 7) << 4;
            #pragma unroll
            for (int dw = 0; dw < 4; dw++) {
                uint32_t voff = vrowoff + (((uint32_t)((dw*16 + vd)*2)) ^ vmask);
                uint32_t h0,h1,h2,h3, g0,g1,g2,g3;
                LDSM4T(h0, h1, h2, h3, sVh + voff);
                LDSM4T(g0, g1, g2, g3, sVl + voff);
                MMA_F16B(o[2*dw],   ph, h0, h1);
                MMA_F16B(o[2*dw],   pl, h0, h1);
                MMA_F16B(o[2*dw],   ph, g0, g1);
                MMA_F16B(o[2*dw+1], ph, h2, h3);
                MMA_F16B(o[2*dw+1], pl, h2, h3);
                MMA_F16B(o[2*dw+1], ph, g2, g3);
            }
        }
    }

    float inv0 = 1.f / l0r, inv1 = 1.f / l1r;
    int row0 = q0 + w*16 + (lane >> 2);
    size_t base0 = ((size_t)(bb*Tq + row0))*Eq + (size_t)hh*64 + ((lane & 3) << 1);
    size_t base1 = base0 + (size_t)8*Eq;
    #pragma unroll
    for (int nf = 0; nf < 8; nf++) {
        uint32_t hv, lv;
        split2h(o[nf][0]*inv0, o[nf][1]*inv0, hv, lv);
        *(uint32_t*)(yhi + base0 + nf*8) = hv;
        *(uint32_t*)(ylo + base0 + nf*8) = lv;
        split2h(o[nf][2]*inv1, o[nf][3]*inv1, hv, lv);
        *(uint32_t*)(yhi + base1 + nf*8) = hv;
        *(uint32_t*)(ylo + base1 + nf*8) = lv;
    }
}

// ---------------- host orchestration ----------------------------------------
extern "C" void kernel_launch(void* const* d_in, const int* in_sizes, int n_in,
                              void* d_out, int out_size)
{
    const int*   x      = (const int*)  d_in[0];
    const float* tok    = (const float*)d_in[2];
    const float* pos    = (const float*)d_in[3];
    const float* ln1g   = (const float*)d_in[4];
    const float* ln1b   = (const float*)d_in[5];
    const float* Wqp    = (const float*)d_in[6];
    const float* bqp    = (const float*)d_in[7];
    const float* Wkp    = (const float*)d_in[8];
    const float* bkp    = (const float*)d_in[9];
    const float* Wvp    = (const float*)d_in[10];
    const float* bvp    = (const float*)d_in[11];
    const float* Wpp    = (const float*)d_in[12];
    const float* bpp    = (const float*)d_in[13];
    const float* ln2g   = (const float*)d_in[14];
    const float* ln2b   = (const float*)d_in[15];
    const float* Wf1p   = (const float*)d_in[16];
    const float* bf1p   = (const float*)d_in[17];
    const float* Wf2p   = (const float*)d_in[18];
    const float* bf2p   = (const float*)d_in[19];
    const float* lnfg   = (const float*)d_in[20];
    const float* lnfb   = (const float*)d_in[21];
    const float* headw  = (const float*)d_in[22];

    float *h, *bqkv;
    cudaGetSymbolAddress((void**)&h, g_h);
    cudaGetSymbolAddress((void**)&bqkv, g_bqkv);

    __half *xnh,*xnl,*qkvh,*qkvl,*yh,*yl,*mlh,*mll;
    cudaGetSymbolAddress((void**)&xnh, g_xn_hi);
    cudaGetSymbolAddress((void**)&xnl, g_xn_lo);
    cudaGetSymbolAddress((void**)&qkvh, g_qkv_hi);
    cudaGetSymbolAddress((void**)&qkvl, g_qkv_lo);
    cudaGetSymbolAddress((void**)&yh,  g_y_hi);
    cudaGetSymbolAddress((void**)&yl,  g_y_lo);
    cudaGetSymbolAddress((void**)&mlh, g_ml_hi);
    cudaGetSymbolAddress((void**)&mll, g_ml_lo);

    __half *wqkv,*wp,*w1,*w2,*wh;
    cudaGetSymbolAddress((void**)&wqkv, g_wqkv);
    cudaGetSymbolAddress((void**)&wp, g_wp);
    cudaGetSymbolAddress((void**)&w1, g_w1);
    cudaGetSymbolAddress((void**)&w2, g_w2);
    cudaGetSymbolAddress((void**)&wh, g_wh);

    cudaFuncSetAttribute(gemm_hf, cudaFuncAttributeMaxDynamicSharedMemorySize, GT_SMEM);
    cudaFuncSetAttribute(attn_fused, cudaFuncAttributeMaxDynamicSharedMemorySize, FA_SMEM);

    convAll<<<147980, 256>>>(Wqp, Wkp, Wvp, Wpp, Wf1p, Wf2p, headw,
                             bqp, bkp, bvp, wqkv, wp, w1, w2, wh, bqkv);
    embed_kernel<<<Mq, 256>>>(x, tok, pos, h);

    dim3 gQKV(E3/128, Mq/128);    // (24, 32)
    dim3 gEE(Eq/128, Mq/128);     // (8, 32)
    dim3 gEF(Fq/128, Mq/128);     // (32, 32)
    dim3 gEV(Vq/128, Mq/128);     // (4, 32)

    for (int l = 0; l < Lq; l++) {
        const size_t oE = (size_t)l*Eq*Eq;
        const size_t oF = (size_t)l*Eq*Fq;

        ln_kernel<<<Mq, 256>>>(h, ln1g + l*Eq, ln1b + l*Eq, xnh, xnl);
        gemm_hf<<<gQKV, 256, GT_SMEM>>>(xnh, xnl, wqkv + (size_t)l*E3*Eq,
                                        bqkv + l*E3, nullptr,
                                        nullptr, qkvh, qkvl, Mq, E3, Eq, 0);

        attn_fused<<<Bq*Hq*8, 128, FA_SMEM>>>(qkvh, qkvl, yh, yl);

        gemm_hf<<<gEE, 256, GT_SMEM>>>(yh, yl, wp+oE, bpp + l*Eq, h,
                                       h, nullptr, nullptr, Mq, Eq, Eq, 0);

        ln_kernel<<<Mq, 256>>>(h, ln2g + l*Eq, ln2b + l*Eq, xnh, xnl);
        gemm_hf<<<gEF, 256, GT_SMEM>>>(xnh, xnl, w1+oF, bf1p + l*Fq, nullptr,
                                       nullptr, mlh, mll, Mq, Fq, Eq, 1);
        gemm_hf<<<gEE, 256, GT_SMEM>>>(mlh, mll, w2+oF, bf2p + l*Eq, h,
                                       h, nullptr, nullptr, Mq, Eq, Fq, 0);
    }

    ln_kernel<<<Mq, 256>>>(h, lnfg, lnfb, xnh, xnl);
    gemm_hf<<<gEV, 256, GT_SMEM>>>(xnh, xnl, wh, nullptr, nullptr,
                                   (float*)d_out, nullptr, nullptr, Mq, Vq, Eq, 0);
}

// round 14
// speedup vs baseline: 1.1291x; 1.1291x over previous
#include <cuda_runtime.h>
#include <cuda_fp16.h>
#include <math.h>
#include <stdint.h>

#define Lq 12
#define Eq 1024
#define Hq 16
#define Tq 512
#define Bq 8
#define Vq 512
#define Fq 4096
#define Dq 64
#define Mq (Bq*Tq)
#define E3 (3*Eq)

// ---------------- scratch ----------------------------------------------------
__device__ float g_h[Mq*Eq];
__device__ float g_bqkv[Lq*E3];
__device__ __half g_xn_hi[Mq*Eq],  g_xn_lo[Mq*Eq];
__device__ __half g_qkv_hi[(size_t)Mq*E3], g_qkv_lo[(size_t)Mq*E3];
__device__ __half g_y_hi [Mq*Eq],  g_y_lo [Mq*Eq];
__device__ __half g_ml_hi[(size_t)Mq*Fq], g_ml_lo[(size_t)Mq*Fq];
__device__ __half g_wqkv[(size_t)Lq*E3*Eq];
__device__ __half g_wp[(size_t)Lq*Eq*Eq];
__device__ __half g_w1[(size_t)Lq*Eq*Fq];
__device__ __half g_w2[(size_t)Lq*Fq*Eq];
__device__ __half g_wh[(size_t)Eq*Vq];

// ---------------- helpers ----------------------------------------------------
__device__ __forceinline__ uint32_t smem_u32(const void* p) {
    uint32_t a;
    asm("{ .reg .u64 t; cvta.to.shared.u64 t, %1; cvt.u32.u64 %0, t; }" : "=r"(a) : "l"(p));
    return a;
}
#define SW128(o) ((o) ^ (((o) >> 3) & 0x70))
#define CP16(dst, src) \
    asm volatile("cp.async.cg.shared.global [%0], [%1], 16;" :: "r"(dst), "l"(src) : "memory")
#define CP_COMMIT() asm volatile("cp.async.commit_group;" ::: "memory")
#define CP_WAIT1()  asm volatile("cp.async.wait_group 1;" ::: "memory")
#define CP_WAIT0()  asm volatile("cp.async.wait_group 0;" ::: "memory")
#define LDSM4(r0, r1, r2, r3, addr) \
    asm volatile("ldmatrix.sync.aligned.m8n8.x4.shared.b16 {%0,%1,%2,%3}, [%4];" \
                 : "=r"(r0), "=r"(r1), "=r"(r2), "=r"(r3) : "r"(addr))
#define LDSM4T(r0, r1, r2, r3, addr) \
    asm volatile("ldmatrix.sync.aligned.m8n8.x4.trans.shared.b16 {%0,%1,%2,%3}, [%4];" \
                 : "=r"(r0), "=r"(r1), "=r"(r2), "=r"(r3) : "r"(addr))
#define MMA_F16(c, a, b) \
    asm volatile("mma.sync.aligned.m16n8k16.row.col.f32.f16.f16.f32 " \
                 "{%0,%1,%2,%3}, {%4,%5,%6,%7}, {%8,%9}, {%0,%1,%2,%3};" \
                 : "+f"((c)[0]), "+f"((c)[1]), "+f"((c)[2]), "+f"((c)[3]) \
                 : "r"((a)[0]), "r"((a)[1]), "r"((a)[2]), "r"((a)[3]), \
                   "r"((b)[0]), "r"((b)[1]))
#define MMA_F16B(c, a, b0, b1) \
    asm volatile("mma.sync.aligned.m16n8k16.row.col.f32.f16.f16.f32 " \
                 "{%0,%1,%2,%3}, {%4,%5,%6,%7}, {%8,%9}, {%0,%1,%2,%3};" \
                 : "+f"((c)[0]), "+f"((c)[1]), "+f"((c)[2]), "+f"((c)[3]) \
                 : "r"((a)[0]), "r"((a)[1]), "r"((a)[2]), "r"((a)[3]), \
                   "r"(b0), "r"(b1))

__device__ __forceinline__ void split2h(float x, float y, uint32_t& h, uint32_t& l) {
    asm("cvt.rn.f16x2.f32 %0, %1, %2;" : "=r"(h) : "f"(y), "f"(x));
    __half2 hh = *reinterpret_cast<__half2*>(&h);
    float hx = __low2float(hh), hy = __high2float(hh);
    asm("cvt.rn.f16x2.f32 %0, %1, %2;" : "=r"(l) : "f"(y - hy), "f"(x - hx));
}

// ---------------- merged weight conversion + bias packing --------------------
__global__ __launch_bounds__(256)
void convAll(const float* __restrict__ Wq, const float* __restrict__ Wk,
             const float* __restrict__ Wv, const float* __restrict__ Wp,
             const float* __restrict__ W1, const float* __restrict__ W2,
             const float* __restrict__ Wh,
             const float* __restrict__ bq, const float* __restrict__ bk,
             const float* __restrict__ bv,
             __half* oqkv, __half* op, __half* o1, __half* o2, __half* oh,
             float* obias)
{
    int b = blockIdx.x;
    int tid = threadIdx.x;
    if (b >= 147968) {
        int l = b - 147968;
        for (int i = tid; i < Eq; i += 256) {
            obias[l*E3 + i]          = bq[l*Eq + i];
            obias[l*E3 + Eq + i]     = bk[l*Eq + i];
            obias[l*E3 + 2*Eq + i]   = bv[l*Eq + i];
        }
        return;
    }
    const float* W; __half* O; int K, N; int rowoff = 0; size_t lstride;
    if (b < 49152) {
        int g = b / 12288; b -= g * 12288; K = Eq; N = Eq;
        if (g < 3) { W = (g==0) ? Wq : (g==1) ? Wk : Wv; O = oqkv; rowoff = g*Eq; lstride = (size_t)E3*Eq; }
        else       { W = Wp; O = op; lstride = (size_t)Eq*Eq; }
    } else if (b < 98304)  { b -= 49152; K = Eq; N = Fq; W = W1; O = o1; lstride = (size_t)Eq*Fq; }
    else if (b < 147456)   { b -= 98304; K = Fq; N = Eq; W = W2; O = o2; lstride = (size_t)Fq*Eq; }
    else                   { b -= 147456; K = Eq; N = Vq; W = Wh; O = oh; lstride = (size_t)Eq*Vq; }
    int tilesN = N >> 5;
    int per = tilesN * (K >> 5);
    int l = b / per; int rem = b - l * per;
    int kt = rem / tilesN, nt = rem - kt * tilesN;
    const float* Wl = W + (size_t)l * K * N;
    __half* Ol = O + (size_t)l * lstride;
    int k0 = kt * 32, n0 = nt * 32;
    __shared__ float t[32][33];
    int r = tid >> 5, c = tid & 31;
    #pragma unroll
    for (int i = 0; i < 4; i++)
        t[r + 8*i][c] = Wl[(size_t)(k0 + r + 8*i) * N + n0 + c];
    __syncthreads();
    #pragma unroll
    for (int i = 0; i < 4; i++)
        Ol[(size_t)(rowoff + n0 + r + 8*i) * K + k0 + c] = __float2half(t[c][r + 8*i]);
}

// ---------------- embedding ---------------------------------------------------
__global__ void embed_kernel(const int* __restrict__ x,
                             const float* __restrict__ tok,
                             const float* __restrict__ pos,
                             float* __restrict__ out)
{
    int row = blockIdx.x;
    int t   = row & (Tq-1);
    int id  = x[row];
    int tid = threadIdx.x;
    float4 a = ((const float4*)(tok + (size_t)id*Eq))[tid];
    float4 p = ((const float4*)(pos + (size_t)t*Eq))[tid];
    float4 o; o.x=a.x+p.x; o.y=a.y+p.y; o.z=a.z+p.z; o.w=a.w+p.w;
    ((float4*)(out + (size_t)row*Eq))[tid] = o;
}

// ---------------- layernorm ---------------------------------------------------
__global__ void ln_kernel(const float* __restrict__ x,
                          const float* __restrict__ g,
                          const float* __restrict__ b,
                          __half* __restrict__ ohi,
                          __half* __restrict__ olo)
{
    int row = blockIdx.x;
    int tid = threadIdx.x;
    const float4* xr = (const float4*)(x + (size_t)row*Eq);
    float4 xv = xr[tid];
    float s  = xv.x + xv.y + xv.z + xv.w;
    float sq = xv.x*xv.x + xv.y*xv.y + xv.z*xv.z + xv.w*xv.w;
    #pragma unroll
    for (int off = 16; off > 0; off >>= 1) {
        s  += __shfl_xor_sync(0xffffffffu, s,  off);
        sq += __shfl_xor_sync(0xffffffffu, sq, off);
    }
    __shared__ float r1[8], r2[8];
    int w = tid >> 5;
    if ((tid & 31) == 0) { r1[w] = s; r2[w] = sq; }
    __syncthreads();
    float ts = 0.f, tq = 0.f;
    #pragma unroll
    for (int i = 0; i < 8; i++) { ts += r1[i]; tq += r2[i]; }
    float mean = ts * (1.0f/Eq);
    float var  = tq * (1.0f/Eq) - mean*mean;
    float rstd = rsqrtf(var + 1e-5f);
    float4 gv = ((const float4*)g)[tid];
    float4 bv = ((const float4*)b)[tid];
    float4 ov;
    ov.x = (xv.x-mean)*rstd*gv.x + bv.x;
    ov.y = (xv.y-mean)*rstd*gv.y + bv.y;
    ov.z = (xv.z-mean)*rstd*gv.z + bv.z;
    ov.w = (xv.w-mean)*rstd*gv.w + bv.w;
    uint32_t h0,h1,l0,l1;
    split2h(ov.x, ov.y, h0, l0);
    split2h(ov.z, ov.w, h1, l1);
    uint2 hv; hv.x = h0; hv.y = h1;
    uint2 lv; lv.x = l0; lv.y = l1;
    ((uint2*)(ohi + (size_t)row*Eq))[tid] = hv;
    ((uint2*)(olo + (size_t)row*Eq))[tid] = lv;
}

// ================ HMMA fp16 GEMM (R8 engine: 2-stage, 2 CTAs/SM) =============
#define ST_STRIDE 49152u
#define GT_SMEM (2*49152)

__device__ __forceinline__ float gelu_exact(float v) {
    return 0.5f * v * (1.0f + erff(v * 0.7071067811865475f));
}

__device__ __forceinline__ void load_stage(
    uint32_t sb, const __half* __restrict__ Ah, const __half* __restrict__ Al,
    const __half* __restrict__ Bh, const uint32_t* soff,
    size_t aBase, size_t bBase, int K)
{
    #pragma unroll
    for (int c = 0; c < 4; c++) {
        size_t ao = aBase + (size_t)(32*c) * K;
        size_t bo = bBase + (size_t)(32*c) * K;
        CP16(sb + soff[c],          Ah + ao);
        CP16(sb + 16384u + soff[c], Al + ao);
        CP16(sb + 32768u + soff[c], Bh + bo);
    }
    CP_COMMIT();
}

__global__ __launch_bounds__(256, 2)
void gemm_hf(const __half* __restrict__ Ah, const __half* __restrict__ Al,
             const __half* __restrict__ Bh,
             const float* __restrict__ bias, const float* __restrict__ res,
             float* __restrict__ C, __half* __restrict__ Chi,
             __half* __restrict__ Clo, int M, int N, int K, int act)
{
    extern __shared__ char smem[];
    const uint32_t sbase = smem_u32(smem);
    const int tid  = threadIdx.x;
    const int wid  = tid >> 5;
    const int lane = tid & 31;
    const int bm = blockIdx.y * 128;
    const int bn = blockIdx.x * 128;

    uint32_t soff[4];
    #pragma unroll
    for (int c = 0; c < 4; c++)
        soff[c] = SW128((uint32_t)((32*c + (tid >> 3))*128 + (tid & 7)*16));
    const size_t aBase0 = (size_t)(bm + (tid >> 3)) * K + (tid & 7)*8;
    const size_t bBase0 = (size_t)(bn + (tid >> 3)) * K + (tid & 7)*8;

    const int m0 = (wid & 3) * 32;
    const int n0 = (wid >> 2) * 64;
    uint32_t aRow[2], aMask[2];
    #pragma unroll
    for (int mt = 0; mt < 2; mt++) {
        int r = m0 + mt*16 + (lane & 15);
        aRow[mt]  = (uint32_t)r * 128u;
        aMask[mt] = (uint32_t)(r & 7) << 4;
    }
    const uint32_t kA = ((uint32_t)(lane >> 4)) << 4;
    uint32_t bRow[4], bMask[4];
    #pragma unroll
    for (int p = 0; p < 4; p++) {
        int r = n0 + p*16 + (((lane >> 4) & 1) << 3) + (lane & 7);
        bRow[p]  = (uint32_t)r * 128u;
        bMask[p] = (uint32_t)(r & 7) << 4;
    }
    const uint32_t kB = ((uint32_t)(lane & 8)) << 1;

    float acc[2][8][4];
    #pragma unroll
    for (int mt = 0; mt < 2; mt++)
        #pragma unroll
        for (int nt = 0; nt < 8; nt++)
            #pragma unroll
            for (int c = 0; c < 4; c++) acc[mt][nt][c] = 0.f;

    const int nst = K >> 6;
    load_stage(sbase, Ah, Al, Bh, soff, aBase0, bBase0, K);
    if (nst > 1)
        load_stage(sbase + ST_STRIDE, Ah, Al, Bh, soff, aBase0 + 64, bBase0 + 64, K);

    for (int s = 0; s < nst; s++) {
        if (s + 1 < nst) CP_WAIT1(); else CP_WAIT0();
        __syncthreads();
        {
            const uint32_t tb = sbase + (uint32_t)(s & 1)*ST_STRIDE;
            const uint32_t bufAh = tb, bufAl = tb + 16384u, bufBh = tb + 32768u;
            #pragma unroll
            for (int ks = 0; ks < 4; ks++) {
                uint32_t ah[2][4], al[2][4];
                #pragma unroll
                for (int mt = 0; mt < 2; mt++) {
                    uint32_t co  = (uint32_t)(ks*32) + kA;
                    uint32_t off = aRow[mt] + (co ^ aMask[mt]);
                    LDSM4(ah[mt][0], ah[mt][1], ah[mt][2], ah[mt][3], bufAh + off);
                    LDSM4(al[mt][0], al[mt][1], al[mt][2], al[mt][3], bufAl + off);
                }
                uint32_t bh[8][2];
                #pragma unroll
                for (int p = 0; p < 4; p++) {
                    uint32_t co  = (uint32_t)(ks*32) + kB;
                    uint32_t off = bRow[p] + (co ^ bMask[p]);
                    uint32_t t0,t1,t2,t3;
                    LDSM4(t0, t1, t2, t3, bufBh + off);
                    bh[2*p][0]=t0; bh[2*p][1]=t1; bh[2*p+1][0]=t2; bh[2*p+1][1]=t3;
                }
                // term-major: 16 independent MMAs between acc reuses
                #pragma unroll
                for (int mt = 0; mt < 2; mt++)
                    #pragma unroll
                    for (int nt = 0; nt < 8; nt++)
                        MMA_F16(acc[mt][nt], ah[mt], bh[nt]);
                #pragma unroll
                for (int mt = 0; mt < 2; mt++)
                    #pragma unroll
                    for (int nt = 0; nt < 8; nt++)
                        MMA_F16(acc[mt][nt], al[mt], bh[nt]);
            }
        }
        if (s + 2 < nst) {
            __syncthreads();
            load_stage(sbase + (uint32_t)(s & 1)*ST_STRIDE, Ah, Al, Bh, soff,
                       aBase0 + (size_t)(s + 2)*64, bBase0 + (size_t)(s + 2)*64, K);
        }
    }

    #pragma unroll
    for (int mt = 0; mt < 2; mt++) {
        #pragma unroll
        for (int nt = 0; nt < 8; nt++) {
            int mrow = bm + m0 + mt*16 + (lane >> 2);
            int ncol = bn + n0 + nt*8 + ((lane & 3) << 1);
            #pragma unroll
            for (int half = 0; half < 2; half++) {
                int m = mrow + half*8;
                float v0 = acc[mt][nt][half*2 + 0];
                float v1 = acc[mt][nt][half*2 + 1];
                if (bias) { v0 += bias[ncol]; v1 += bias[ncol + 1]; }
                if (act)  { v0 = gelu_exact(v0); v1 = gelu_exact(v1); }
                if (res) {
                    const float2 rr = *(const float2*)(res + (size_t)m * N + ncol);
                    v0 += rr.x; v1 += rr.y;
                }
                if (C) {
                    float2 o; o.x = v0; o.y = v1;
                    *(float2*)(C + (size_t)m * N + ncol) = o;
                }
                if (Chi) {
                    uint32_t hh, ll;
                    split2h(v0, v1, hh, ll);
                    *(uint32_t*)(Chi + (size_t)m * N + ncol) = hh;
                    *(uint32_t*)(Clo + (size_t)m * N + ncol) = ll;
                }
            }
        }
    }
}

// ================ fused flash attention (packed QKV input) ==================
#define FA_SMEM 65536

__global__ __launch_bounds__(128)
void attn_fused(const __half* __restrict__ qkvh, const __half* __restrict__ qkvl,
                __half* __restrict__ yhi, __half* __restrict__ ylo)
{
    const int qt = blockIdx.x & 7;
    const int bh = blockIdx.x >> 3;
    const int hh = bh & (Hq-1);
    const int bb = bh >> 4;
    const int q0 = qt * 64;
    const int tid = threadIdx.x, lane = tid & 31, w = tid >> 5;

    extern __shared__ char smem[];
    const uint32_t sb = smem_u32(smem);
    const uint32_t sQh = sb, sQl = sb + 8192u;

    const int lr = tid >> 1, lc = tid & 1;
    uint32_t ldst[4];
    #pragma unroll
    for (int i = 0; i < 4; i++)
        ldst[i] = SW128((uint32_t)(lr*128 + lc*64 + i*16));
    const size_t coloff = (size_t)hh*64 + lc*32;

    {   // Q tile
        size_t rb = ((size_t)(bb*Tq + q0 + lr))*E3 + coloff;
        #pragma unroll
        for (int i = 0; i < 4; i++) CP16(sQh + ldst[i], qkvh + rb + i*8);
        #pragma unroll
        for (int i = 0; i < 4; i++) CP16(sQl + ldst[i], qkvl + rb + i*8);
        CP_COMMIT();
    }
    {   // KV tile 0
        size_t rb = ((size_t)(bb*Tq + lr))*E3 + coloff;
        uint32_t kvb = sb + 16384u;
        #pragma unroll
        for (int i = 0; i < 4; i++) CP16(kvb + ldst[i],          qkvh + rb + Eq   + i*8);
        #pragma unroll
        for (int i = 0; i < 4; i++) CP16(kvb + 8192u + ldst[i],  qkvh + rb + 2*Eq + i*8);
        #pragma unroll
        for (int i = 0; i < 4; i++) CP16(kvb + 16384u + ldst[i], qkvl + rb + 2*Eq + i*8);
        CP_COMMIT();
    }

    const int arow = w*16 + (lane & 15);
    const uint32_t aRow = (uint32_t)arow * 128u;
    const uint32_t aMask = (uint32_t)(arow & 7) << 4;
    const uint32_t kA = ((uint32_t)(lane >> 4)) << 4;
    uint32_t bRow[4], bMask[4];
    #pragma unroll
    for (int p = 0; p < 4; p++) {
        int r = p*16 + (((lane >> 4) & 1) << 3) + (lane & 7);
        bRow[p]  = (uint32_t)r * 128u;
        bMask[p] = (uint32_t)(r & 7) << 4;
    }
    const uint32_t kB = ((uint32_t)(lane & 8)) << 1;
    const int vsub = lane >> 3, vrow = lane & 7;
    const int vtok = ((vsub & 1) << 3) + vrow;
    const int vd   = (vsub >> 1) << 3;

    float o[8][4];
    #pragma unroll
    for (int nf = 0; nf < 8; nf++)
        #pragma unroll
        for (int e = 0; e < 4; e++) o[nf][e] = 0.f;
    float m0r = -1e30f, m1r = -1e30f, l0r = 0.f, l1r = 0.f;

    const int nkt = qt + 1;
    for (int kt = 0; kt < nkt; kt++) {
        CP_WAIT0();
        __syncthreads();
        if (kt + 1 < nkt) {
            size_t rb = ((size_t)(bb*Tq + (kt+1)*64 + lr))*E3 + coloff;
            uint32_t kvb = sb + 16384u + (uint32_t)((kt+1) & 1)*24576u;
            #pragma unroll
            for (int i = 0; i < 4; i++) CP16(kvb + ldst[i],          qkvh + rb + Eq   + i*8);
            #pragma unroll
            for (int i = 0; i < 4; i++) CP16(kvb + 8192u + ldst[i],  qkvh + rb + 2*Eq + i*8);
            #pragma unroll
            for (int i = 0; i < 4; i++) CP16(kvb + 16384u + ldst[i], qkvl + rb + 2*Eq + i*8);
            CP_COMMIT();
        }
        const uint32_t kvb = sb + 16384u + (uint32_t)(kt & 1)*24576u;
        const uint32_t sK = kvb, sVh = kvb + 8192u, sVl = kvb + 16384u;

        float s[8][4];
        #pragma unroll
        for (int nf = 0; nf < 8; nf++)
            #pragma unroll
            for (int e = 0; e < 4; e++) s[nf][e] = 0.f;
        #pragma unroll
        for (int ks = 0; ks < 4; ks++) {
            uint32_t co = (uint32_t)(ks*32);
            uint32_t aoff = aRow + ((co + kA) ^ aMask);
            uint32_t ahr[4], alr[4];
            LDSM4(ahr[0], ahr[1], ahr[2], ahr[3], sQh + aoff);
            LDSM4(alr[0], alr[1], alr[2], alr[3], sQl + aoff);
            uint32_t bk[8][2];
            #pragma unroll
            for (int p = 0; p < 4; p++) {
                uint32_t off = bRow[p] + ((co + kB) ^ bMask[p]);
                uint32_t t0,t1,t2,t3;
                LDSM4(t0, t1, t2, t3, sK + off);
                bk[2*p][0]=t0; bk[2*p][1]=t1; bk[2*p+1][0]=t2; bk[2*p+1][1]=t3;
            }
            #pragma unroll
            for (int nf = 0; nf < 8; nf++)
                MMA_F16(s[nf], ahr, bk[nf]);
            #pragma unroll
            for (int nf = 0; nf < 8; nf++)
                MMA_F16(s[nf], alr, bk[nf]);
        }
        #pragma unroll
        for (int nf = 0; nf < 8; nf++)
            #pragma unroll
            for (int e = 0; e < 4; e++) s[nf][e] *= 0.125f;
        if (kt == qt) {
            int r0l = w*16 + (lane >> 2);
            #pragma unroll
            for (int nf = 0; nf < 8; nf++) {
                int col = nf*8 + ((lane & 3) << 1);
                if (col     > r0l)     s[nf][0] = -1e30f;
                if (col + 1 > r0l)     s[nf][1] = -1e30f;
                if (col     > r0l + 8) s[nf][2] = -1e30f;
                if (col + 1 > r0l + 8) s[nf][3] = -1e30f;
            }
        }
        float mx0 = -1e30f, mx1 = -1e30f;
        #pragma unroll
        for (int nf = 0; nf < 8; nf++) {
            mx0 = fmaxf(mx0, fmaxf(s[nf][0], s[nf][1]));
            mx1 = fmaxf(mx1, fmaxf(s[nf][2], s[nf][3]));
        }
        mx0 = fmaxf(mx0, __shfl_xor_sync(0xffffffffu, mx0, 1));
        mx0 = fmaxf(mx0, __shfl_xor_sync(0xffffffffu, mx0, 2));
        mx1 = fmaxf(mx1, __shfl_xor_sync(0xffffffffu, mx1, 1));
        mx1 = fmaxf(mx1, __shfl_xor_sync(0xffffffffu, mx1, 2));
        float mn0 = fmaxf(m0r, mx0), mn1 = fmaxf(m1r, mx1);
        float f0 = __expf(m0r - mn0), f1 = __expf(m1r - mn1);
        m0r = mn0; m1r = mn1;
        float ps0 = 0.f, ps1 = 0.f;
        #pragma unroll
        for (int nf = 0; nf < 8; nf++) {
            s[nf][0] = __expf(s[nf][0] - mn0); ps0 += s[nf][0];
            s[nf][1] = __expf(s[nf][1] - mn0); ps0 += s[nf][1];
            s[nf][2] = __expf(s[nf][2] - mn1); ps1 += s[nf][2];
            s[nf][3] = __expf(s[nf][3] - mn1); ps1 += s[nf][3];
        }
        ps0 += __shfl_xor_sync(0xffffffffu, ps0, 1);
        ps0 += __shfl_xor_sync(0xffffffffu, ps0, 2);
        ps1 += __shfl_xor_sync(0xffffffffu, ps1, 1);
        ps1 += __shfl_xor_sync(0xffffffffu, ps1, 2);
        l0r = l0r*f0 + ps0;
        l1r = l1r*f1 + ps1;
        #pragma unroll
        for (int nf = 0; nf < 8; nf++) {
            o[nf][0] *= f0; o[nf][1] *= f0;
            o[nf][2] *= f1; o[nf][3] *= f1;
        }
        #pragma unroll
        for (int kf = 0; kf < 4; kf++) {
            uint32_t ph[4], pl[4];
            split2h(s[2*kf][0],   s[2*kf][1],   ph[0], pl[0]);
            split2h(s[2*kf][2],   s[2*kf][3],   ph[1], pl[1]);
            split2h(s[2*kf+1][0], s[2*kf+1][1], ph[2], pl[2]);
            split2h(s[2*kf+1][2], s[2*kf+1][3], ph[3], pl[3]);
            int tok = kf*16 + vtok;
            uint32_t vrowoff = (uint32_t)tok * 128u;
            uint32_t vmask   = (uint32_t)(tok & 7) << 4;
            #pragma unroll
            for (int dw = 0; dw < 4; dw++) {
                uint32_t voff = vrowoff + (((uint32_t)((dw*16 + vd)*2)) ^ vmask);
                uint32_t h0,h1,h2,h3, g0,g1,g2,g3;
                LDSM4T(h0, h1, h2, h3, sVh + voff);
                LDSM4T(g0, g1, g2, g3, sVl + voff);
                MMA_F16B(o[2*dw],   ph, h0, h1);
                MMA_F16B(o[2*dw],   pl, h0, h1);
                MMA_F16B(o[2*dw],   ph, g0, g1);
                MMA_F16B(o[2*dw+1], ph, h2, h3);
                MMA_F16B(o[2*dw+1], pl, h2, h3);
                MMA_F16B(o[2*dw+1], ph, g2, g3);
            }
        }
    }

    float inv0 = 1.f / l0r, inv1 = 1.f / l1r;
    int row0 = q0 + w*16 + (lane >> 2);
    size_t base0 = ((size_t)(bb*Tq + row0))*Eq + (size_t)hh*64 + ((lane & 3) << 1);
    size_t base1 = base0 + (size_t)8*Eq;
    #pragma unroll
    for (int nf = 0; nf < 8; nf++) {
        uint32_t hv, lv;
        split2h(o[nf][0]*inv0, o[nf][1]*inv0, hv, lv);
        *(uint32_t*)(yhi + base0 + nf*8) = hv;
        *(uint32_t*)(ylo + base0 + nf*8) = lv;
        split2h(o[nf][2]*inv1, o[nf][3]*inv1, hv, lv);
        *(uint32_t*)(yhi + base1 + nf*8) = hv;
        *(uint32_t*)(ylo + base1 + nf*8) = lv;
    }
}

// ---------------- host orchestration ----------------------------------------
extern "C" void kernel_launch(void* const* d_in, const int* in_sizes, int n_in,
                              void* d_out, int out_size)
{
    const int*   x      = (const int*)  d_in[0];
    const float* tok    = (const float*)d_in[2];
    const float* pos    = (const float*)d_in[3];
    const float* ln1g   = (const float*)d_in[4];
    const float* ln1b   = (const float*)d_in[5];
    const float* Wqp    = (const float*)d_in[6];
    const float* bqp    = (const float*)d_in[7];
    const float* Wkp    = (const float*)d_in[8];
    const float* bkp    = (const float*)d_in[9];
    const float* Wvp    = (const float*)d_in[10];
    const float* bvp    = (const float*)d_in[11];
    const float* Wpp    = (const float*)d_in[12];
    const float* bpp    = (const float*)d_in[13];
    const float* ln2g   = (const float*)d_in[14];
    const float* ln2b   = (const float*)d_in[15];
    const float* Wf1p   = (const float*)d_in[16];
    const float* bf1p   = (const float*)d_in[17];
    const float* Wf2p   = (const float*)d_in[18];
    const float* bf2p   = (const float*)d_in[19];
    const float* lnfg   = (const float*)d_in[20];
    const float* lnfb   = (const float*)d_in[21];
    const float* headw  = (const float*)d_in[22];

    float *h, *bqkv;
    cudaGetSymbolAddress((void**)&h, g_h);
    cudaGetSymbolAddress((void**)&bqkv, g_bqkv);

    __half *xnh,*xnl,*qkvh,*qkvl,*yh,*yl,*mlh,*mll;
    cudaGetSymbolAddress((void**)&xnh, g_xn_hi);
    cudaGetSymbolAddress((void**)&xnl, g_xn_lo);
    cudaGetSymbolAddress((void**)&qkvh, g_qkv_hi);
    cudaGetSymbolAddress((void**)&qkvl, g_qkv_lo);
    cudaGetSymbolAddress((void**)&yh,  g_y_hi);
    cudaGetSymbolAddress((void**)&yl,  g_y_lo);
    cudaGetSymbolAddress((void**)&mlh, g_ml_hi);
    cudaGetSymbolAddress((void**)&mll, g_ml_lo);

    __half *wqkv,*wp,*w1,*w2,*wh;
    cudaGetSymbolAddress((void**)&wqkv, g_wqkv);
    cudaGetSymbolAddress((void**)&wp, g_wp);
    cudaGetSymbolAddress((void**)&w1, g_w1);
    cudaGetSymbolAddress((void**)&w2, g_w2);
    cudaGetSymbolAddress((void**)&wh, g_wh);

    cudaFuncSetAttribute(gemm_hf, cudaFuncAttributeMaxDynamicSharedMemorySize, GT_SMEM);
    cudaFuncSetAttribute(attn_fused, cudaFuncAttributeMaxDynamicSharedMemorySize, FA_SMEM);

    convAll<<<147980, 256>>>(Wqp, Wkp, Wvp, Wpp, Wf1p, Wf2p, headw,
                             bqp, bkp, bvp, wqkv, wp, w1, w2, wh, bqkv);
    embed_kernel<<<Mq, 256>>>(x, tok, pos, h);

    dim3 gQKV(E3/128, Mq/128);    // (24, 32)
    dim3 gEE(Eq/128, Mq/128);     // (8, 32)
    dim3 gEF(Fq/128, Mq/128);     // (32, 32)
    dim3 gEV(Vq/128, Mq/128);     // (4, 32)

    for (int l = 0; l < Lq; l++) {
        const size_t oE = (size_t)l*Eq*Eq;
        const size_t oF = (size_t)l*Eq*Fq;

        ln_kernel<<<Mq, 256>>>(h, ln1g + l*Eq, ln1b + l*Eq, xnh, xnl);
        gemm_hf<<<gQKV, 256, GT_SMEM>>>(xnh, xnl, wqkv + (size_t)l*E3*Eq,
                                        bqkv + l*E3, nullptr,
                                        nullptr, qkvh, qkvl, Mq, E3, Eq, 0);

        attn_fused<<<Bq*Hq*8, 128, FA_SMEM>>>(qkvh, qkvl, yh, yl);

        gemm_hf<<<gEE, 256, GT_SMEM>>>(yh, yl, wp+oE, bpp + l*Eq, h,
                                       h, nullptr, nullptr, Mq, Eq, Eq, 0);

        ln_kernel<<<Mq, 256>>>(h, ln2g + l*Eq, ln2b + l*Eq, xnh, xnl);
        gemm_hf<<<gEF, 256, GT_SMEM>>>(xnh, xnl, w1+oF, bf1p + l*Fq, nullptr,
                                       nullptr, mlh, mll, Mq, Fq, Eq, 1);
        gemm_hf<<<gEE, 256, GT_SMEM>>>(mlh, mll, w2+oF, bf2p + l*Eq, h,
                                       h, nullptr, nullptr, Mq, Eq, Fq, 0);
    }

    ln_kernel<<<Mq, 256>>>(h, lnfg, lnfb, xnh, xnl);
    gemm_hf<<<gEV, 256, GT_SMEM>>>(xnh, xnl, wh, nullptr, nullptr,
                                   (float*)d_out, nullptr, nullptr, Mq, Vq, Eq, 0);
}

// round 17
// speedup vs baseline: 1.4023x; 1.2420x over previous
#include <cuda_runtime.h>
#include <cuda_fp16.h>
#include <math.h>
#include <stdint.h>

#define Lq 12
#define Eq 1024
#define Hq 16
#define Tq 512
#define Bq 8
#define Vq 512
#define Fq 4096
#define Dq 64
#define Mq (Bq*Tq)
#define E3 (3*Eq)

// ---------------- scratch ----------------------------------------------------
__device__ float g_h[Mq*Eq];
__device__ float g_bqkv[Lq*E3];
__device__ __half g_xn_hi[Mq*Eq],  g_xn_lo[Mq*Eq];
__device__ __half g_qkv_hi[(size_t)Mq*E3], g_qkv_lo[(size_t)Mq*E3];
__device__ __half g_y_hi [Mq*Eq],  g_y_lo [Mq*Eq];
__device__ __half g_ml_hi[(size_t)Mq*Fq];
__device__ __half g_wqkv[(size_t)Lq*E3*Eq];
__device__ __half g_wp[(size_t)Lq*Eq*Eq];
__device__ __half g_w1[(size_t)Lq*Eq*Fq];
__device__ __half g_w2[(size_t)Lq*Fq*Eq];
__device__ __half g_wh[(size_t)Eq*Vq];

// ---------------- helpers ----------------------------------------------------
__device__ __forceinline__ uint32_t smem_u32(const void* p) {
    uint32_t a;
    asm("{ .reg .u64 t; cvta.to.shared.u64 t, %1; cvt.u32.u64 %0, t; }" : "=r"(a) : "l"(p));
    return a;
}
#define SW128(o) ((o) ^ (((o) >> 3) & 0x70))
#define CP16(dst, src) \
    asm volatile("cp.async.cg.shared.global [%0], [%1], 16;" :: "r"(dst), "l"(src) : "memory")
#define CP_COMMIT() asm volatile("cp.async.commit_group;" ::: "memory")
#define CP_WAIT1()  asm volatile("cp.async.wait_group 1;" ::: "memory")
#define CP_WAIT0()  asm volatile("cp.async.wait_group 0;" ::: "memory")
#define LDSM4(r0, r1, r2, r3, addr) \
    asm volatile("ldmatrix.sync.aligned.m8n8.x4.shared.b16 {%0,%1,%2,%3}, [%4];" \
                 : "=r"(r0), "=r"(r1), "=r"(r2), "=r"(r3) : "r"(addr))
#define LDSM4T(r0, r1, r2, r3, addr) \
    asm volatile("ldmatrix.sync.aligned.m8n8.x4.trans.shared.b16 {%0,%1,%2,%3}, [%4];" \
                 : "=r"(r0), "=r"(r1), "=r"(r2), "=r"(r3) : "r"(addr))
#define MMA_F16(c, a, b) \
    asm volatile("mma.sync.aligned.m16n8k16.row.col.f32.f16.f16.f32 " \
                 "{%0,%1,%2,%3}, {%4,%5,%6,%7}, {%8,%9}, {%0,%1,%2,%3};" \
                 : "+f"((c)[0]), "+f"((c)[1]), "+f"((c)[2]), "+f"((c)[3]) \
                 : "r"((a)[0]), "r"((a)[1]), "r"((a)[2]), "r"((a)[3]), \
                   "r"((b)[0]), "r"((b)[1]))
#define MMA_F16B(c, a, b0, b1) \
    asm volatile("mma.sync.aligned.m16n8k16.row.col.f32.f16.f16.f32 " \
                 "{%0,%1,%2,%3}, {%4,%5,%6,%7}, {%8,%9}, {%0,%1,%2,%3};" \
                 : "+f"((c)[0]), "+f"((c)[1]), "+f"((c)[2]), "+f"((c)[3]) \
                 : "r"((a)[0]), "r"((a)[1]), "r"((a)[2]), "r"((a)[3]), \
                   "r"(b0), "r"(b1))

__device__ __forceinline__ void split2h(float x, float y, uint32_t& h, uint32_t& l) {
    asm("cvt.rn.f16x2.f32 %0, %1, %2;" : "=r"(h) : "f"(y), "f"(x));
    __half2 hh = *reinterpret_cast<__half2*>(&h);
    float hx = __low2float(hh), hy = __high2float(hh);
    asm("cvt.rn.f16x2.f32 %0, %1, %2;" : "=r"(l) : "f"(y - hy), "f"(x - hx));
}

// ---------------- merged weight conversion + bias packing --------------------
__global__ __launch_bounds__(256)
void convAll(const float* __restrict__ Wq, const float* __restrict__ Wk,
             const float* __restrict__ Wv, const float* __restrict__ Wp,
             const float* __restrict__ W1, const float* __restrict__ W2,
             const float* __restrict__ Wh,
             const float* __restrict__ bq, const float* __restrict__ bk,
             const float* __restrict__ bv,
             __half* oqkv, __half* op, __half* o1, __half* o2, __half* oh,
             float* obias)
{
    int b = blockIdx.x;
    int tid = threadIdx.x;
    if (b >= 147968) {
        int l = b - 147968;
        for (int i = tid; i < Eq; i += 256) {
            obias[l*E3 + i]          = bq[l*Eq + i];
            obias[l*E3 + Eq + i]     = bk[l*Eq + i];
            obias[l*E3 + 2*Eq + i]   = bv[l*Eq + i];
        }
        return;
    }
    const float* W; __half* O; int K, N; int rowoff = 0; size_t lstride;
    if (b < 49152) {
        int g = b / 12288; b -= g * 12288; K = Eq; N = Eq;
        if (g < 3) { W = (g==0) ? Wq : (g==1) ? Wk : Wv; O = oqkv; rowoff = g*Eq; lstride = (size_t)E3*Eq; }
        else       { W = Wp; O = op; lstride = (size_t)Eq*Eq; }
    } else if (b < 98304)  { b -= 49152; K = Eq; N = Fq; W = W1; O = o1; lstride = (size_t)Eq*Fq; }
    else if (b < 147456)   { b -= 98304; K = Fq; N = Eq; W = W2; O = o2; lstride = (size_t)Fq*Eq; }
    else                   { b -= 147456; K = Eq; N = Vq; W = Wh; O = oh; lstride = (size_t)Eq*Vq; }
    int tilesN = N >> 5;
    int per = tilesN * (K >> 5);
    int l = b / per; int rem = b - l * per;
    int kt = rem / tilesN, nt = rem - kt * tilesN;
    const float* Wl = W + (size_t)l * K * N;
    __half* Ol = O + (size_t)l * lstride;
    int k0 = kt * 32, n0 = nt * 32;
    __shared__ float t[32][33];
    int r = tid >> 5, c = tid & 31;
    #pragma unroll
    for (int i = 0; i < 4; i++)
        t[r + 8*i][c] = Wl[(size_t)(k0 + r + 8*i) * N + n0 + c];
    __syncthreads();
    #pragma unroll
    for (int i = 0; i < 4; i++)
        Ol[(size_t)(rowoff + n0 + r + 8*i) * K + k0 + c] = __float2half(t[c][r + 8*i]);
}

// ---------------- embedding ---------------------------------------------------
__global__ void embed_kernel(const int* __restrict__ x,
                             const float* __restrict__ tok,
                             const float* __restrict__ pos,
                             float* __restrict__ out)
{
    int row = blockIdx.x;
    int t   = row & (Tq-1);
    int id  = x[row];
    int tid = threadIdx.x;
    float4 a = ((const float4*)(tok + (size_t)id*Eq))[tid];
    float4 p = ((const float4*)(pos + (size_t)t*Eq))[tid];
    float4 o; o.x=a.x+p.x; o.y=a.y+p.y; o.z=a.z+p.z; o.w=a.w+p.w;
    ((float4*)(out + (size_t)row*Eq))[tid] = o;
}

// ---------------- layernorm ---------------------------------------------------
__global__ void ln_kernel(const float* __restrict__ x,
                          const float* __restrict__ g,
                          const float* __restrict__ b,
                          __half* __restrict__ ohi,
                          __half* __restrict__ olo)
{
    int row = blockIdx.x;
    int tid = threadIdx.x;
    const float4* xr = (const float4*)(x + (size_t)row*Eq);
    float4 xv = xr[tid];
    float s  = xv.x + xv.y + xv.z + xv.w;
    float sq = xv.x*xv.x + xv.y*xv.y + xv.z*xv.z + xv.w*xv.w;
    #pragma unroll
    for (int off = 16; off > 0; off >>= 1) {
        s  += __shfl_xor_sync(0xffffffffu, s,  off);
        sq += __shfl_xor_sync(0xffffffffu, sq, off);
    }
    __shared__ float r1[8], r2[8];
    int w = tid >> 5;
    if ((tid & 31) == 0) { r1[w] = s; r2[w] = sq; }
    __syncthreads();
    float ts = 0.f, tq = 0.f;
    #pragma unroll
    for (int i = 0; i < 8; i++) { ts += r1[i]; tq += r2[i]; }
    float mean = ts * (1.0f/Eq);
    float var  = tq * (1.0f/Eq) - mean*mean;
    float rstd = rsqrtf(var + 1e-5f);
    float4 gv = ((const float4*)g)[tid];
    float4 bv = ((const float4*)b)[tid];
    float4 ov;
    ov.x = (xv.x-mean)*rstd*gv.x + bv.x;
    ov.y = (xv.y-mean)*rstd*gv.y + bv.y;
    ov.z = (xv.z-mean)*rstd*gv.z + bv.z;
    ov.w = (xv.w-mean)*rstd*gv.w + bv.w;
    uint32_t h0,h1,l0,l1;
    split2h(ov.x, ov.y, h0, l0);
    split2h(ov.z, ov.w, h1, l1);
    uint2 hv; hv.x = h0; hv.y = h1;
    uint2 lv; lv.x = l0; lv.y = l1;
    ((uint2*)(ohi + (size_t)row*Eq))[tid] = hv;
    ((uint2*)(olo + (size_t)row*Eq))[tid] = lv;
}

// ================ HMMA fp16 GEMM (R8/R14 engine; optional 1-term mode) =======
#define ST_STRIDE 49152u
#define GT_SMEM (2*49152)

__device__ __forceinline__ float gelu_exact(float v) {
    return 0.5f * v * (1.0f + erff(v * 0.7071067811865475f));
}

__device__ __forceinline__ void load_stage(
    uint32_t sb, const __half* __restrict__ Ah, const __half* __restrict__ Al,
    const __half* __restrict__ Bh, const uint32_t* soff,
    size_t aBase, size_t bBase, int K)
{
    #pragma unroll
    for (int c = 0; c < 4; c++) {
        size_t ao = aBase + (size_t)(32*c) * K;
        size_t bo = bBase + (size_t)(32*c) * K;
        CP16(sb + soff[c],          Ah + ao);
        if (Al) CP16(sb + 16384u + soff[c], Al + ao);
        CP16(sb + 32768u + soff[c], Bh + bo);
    }
    CP_COMMIT();
}

__global__ __launch_bounds__(256, 2)
void gemm_hf(const __half* __restrict__ Ah, const __half* __restrict__ Al,
             const __half* __restrict__ Bh,
             const float* __restrict__ bias, const float* __restrict__ res,
             float* __restrict__ C, __half* __restrict__ Chi,
             __half* __restrict__ Clo, int M, int N, int K, int act)
{
    extern __shared__ char smem[];
    const uint32_t sbase = smem_u32(smem);
    const int tid  = threadIdx.x;
    const int wid  = tid >> 5;
    const int lane = tid & 31;
    const int bm = blockIdx.y * 128;
    const int bn = blockIdx.x * 128;
    const bool hasLo = (Al != nullptr);

    uint32_t soff[4];
    #pragma unroll
    for (int c = 0; c < 4; c++)
        soff[c] = SW128((uint32_t)((32*c + (tid >> 3))*128 + (tid & 7)*16));
    const size_t aBase0 = (size_t)(bm + (tid >> 3)) * K + (tid & 7)*8;
    const size_t bBase0 = (size_t)(bn + (tid >> 3)) * K + (tid & 7)*8;

    const int m0 = (wid & 3) * 32;
    const int n0 = (wid >> 2) * 64;
    uint32_t aRow[2], aMask[2];
    #pragma unroll
    for (int mt = 0; mt < 2; mt++) {
        int r = m0 + mt*16 + (lane & 15);
        aRow[mt]  = (uint32_t)r * 128u;
        aMask[mt] = (uint32_t)(r & 7) << 4;
    }
    const uint32_t kA = ((uint32_t)(lane >> 4)) << 4;
    uint32_t bRow[4], bMask[4];
    #pragma unroll
    for (int p = 0; p < 4; p++) {
        int r = n0 + p*16 + (((lane >> 4) & 1) << 3) + (lane & 7);
        bRow[p]  = (uint32_t)r * 128u;
        bMask[p] = (uint32_t)(r & 7) << 4;
    }
    const uint32_t kB = ((uint32_t)(lane & 8)) << 1;

    float acc[2][8][4];
    #pragma unroll
    for (int mt = 0; mt < 2; mt++)
        #pragma unroll
        for (int nt = 0; nt < 8; nt++)
            #pragma unroll
            for (int c = 0; c < 4; c++) acc[mt][nt][c] = 0.f;

    const int nst = K >> 6;
    load_stage(sbase, Ah, Al, Bh, soff, aBase0, bBase0, K);
    if (nst > 1)
        load_stage(sbase + ST_STRIDE, Ah, Al, Bh, soff, aBase0 + 64, bBase0 + 64, K);

    for (int s = 0; s < nst; s++) {
        if (s + 1 < nst) CP_WAIT1(); else CP_WAIT0();
        __syncthreads();
        {
            const uint32_t tb = sbase + (uint32_t)(s & 1)*ST_STRIDE;
            const uint32_t bufAh = tb, bufAl = tb + 16384u, bufBh = tb + 32768u;
            #pragma unroll
            for (int ks = 0; ks < 4; ks++) {
                uint32_t ah[2][4], al[2][4];
                #pragma unroll
                for (int mt = 0; mt < 2; mt++) {
                    uint32_t co  = (uint32_t)(ks*32) + kA;
                    uint32_t off = aRow[mt] + (co ^ aMask[mt]);
                    LDSM4(ah[mt][0], ah[mt][1], ah[mt][2], ah[mt][3], bufAh + off);
                    if (hasLo)
                        LDSM4(al[mt][0], al[mt][1], al[mt][2], al[mt][3], bufAl + off);
                }
                uint32_t bh[8][2];
                #pragma unroll
                for (int p = 0; p < 4; p++) {
                    uint32_t co  = (uint32_t)(ks*32) + kB;
                    uint32_t off = bRow[p] + (co ^ bMask[p]);
                    uint32_t t0,t1,t2,t3;
                    LDSM4(t0, t1, t2, t3, bufBh + off);
                    bh[2*p][0]=t0; bh[2*p][1]=t1; bh[2*p+1][0]=t2; bh[2*p+1][1]=t3;
                }
                #pragma unroll
                for (int mt = 0; mt < 2; mt++)
                    #pragma unroll
                    for (int nt = 0; nt < 8; nt++)
                        MMA_F16(acc[mt][nt], ah[mt], bh[nt]);
                if (hasLo) {
                    #pragma unroll
                    for (int mt = 0; mt < 2; mt++)
                        #pragma unroll
                        for (int nt = 0; nt < 8; nt++)
                            MMA_F16(acc[mt][nt], al[mt], bh[nt]);
                }
            }
        }
        if (s + 2 < nst) {
            __syncthreads();
            load_stage(sbase + (uint32_t)(s & 1)*ST_STRIDE, Ah, Al, Bh, soff,
                       aBase0 + (size_t)(s + 2)*64, bBase0 + (size_t)(s + 2)*64, K);
        }
    }

    #pragma unroll
    for (int mt = 0; mt < 2; mt++) {
        #pragma unroll
        for (int nt = 0; nt < 8; nt++) {
            int mrow = bm + m0 + mt*16 + (lane >> 2);
            int ncol = bn + n0 + nt*8 + ((lane & 3) << 1);
            #pragma unroll
            for (int half = 0; half < 2; half++) {
                int m = mrow + half*8;
                float v0 = acc[mt][nt][half*2 + 0];
                float v1 = acc[mt][nt][half*2 + 1];
                if (bias) { v0 += bias[ncol]; v1 += bias[ncol + 1]; }
                if (act)  { v0 = gelu_exact(v0); v1 = gelu_exact(v1); }
                if (res) {
                    const float2 rr = *(const float2*)(res + (size_t)m * N + ncol);
                    v0 += rr.x; v1 += rr.y;
                }
                if (C) {
                    float2 o; o.x = v0; o.y = v1;
                    *(float2*)(C + (size_t)m * N + ncol) = o;
                }
                if (Chi) {
                    if (Clo) {
                        uint32_t hh, ll;
                        split2h(v0, v1, hh, ll);
                        *(uint32_t*)(Chi + (size_t)m * N + ncol) = hh;
                        *(uint32_t*)(Clo + (size_t)m * N + ncol) = ll;
                    } else {
                        uint32_t hh;
                        asm("cvt.rn.f16x2.f32 %0, %1, %2;" : "=r"(hh) : "f"(v1), "f"(v0));
                        *(uint32_t*)(Chi + (size_t)m * N + ncol) = hh;
                    }
                }
            }
        }
    }
}

// ================ fused flash attention (packed QKV input) ==================
#define FA_SMEM 65536

__global__ __launch_bounds__(128)
void attn_fused(const __half* __restrict__ qkvh, const __half* __restrict__ qkvl,
                __half* __restrict__ yhi, __half* __restrict__ ylo)
{
    const int qt = blockIdx.x & 7;
    const int bh = blockIdx.x >> 3;
    const int hh = bh & (Hq-1);
    const int bb = bh >> 4;
    const int q0 = qt * 64;
    const int tid = threadIdx.x, lane = tid & 31, w = tid >> 5;

    extern __shared__ char smem[];
    const uint32_t sb = smem_u32(smem);
    const uint32_t sQh = sb, sQl = sb + 8192u;

    const int lr = tid >> 1, lc = tid & 1;
    uint32_t ldst[4];
    #pragma unroll
    for (int i = 0; i < 4; i++)
        ldst[i] = SW128((uint32_t)(lr*128 + lc*64 + i*16));
    const size_t coloff = (size_t)hh*64 + lc*32;

    {   // Q tile
        size_t rb = ((size_t)(bb*Tq + q0 + lr))*E3 + coloff;
        #pragma unroll
        for (int i = 0; i < 4; i++) CP16(sQh + ldst[i], qkvh + rb + i*8);
        #pragma unroll
        for (int i = 0; i < 4; i++) CP16(sQl + ldst[i], qkvl + rb + i*8);
        CP_COMMIT();
    }
    {   // KV tile 0
        size_t rb = ((size_t)(bb*Tq + lr))*E3 + coloff;
        uint32_t kvb = sb + 16384u;
        #pragma unroll
        for (int i = 0; i < 4; i++) CP16(kvb + ldst[i],          qkvh + rb + Eq   + i*8);
        #pragma unroll
        for (int i = 0; i < 4; i++) CP16(kvb + 8192u + ldst[i],  qkvh + rb + 2*Eq + i*8);
        #pragma unroll
        for (int i = 0; i < 4; i++) CP16(kvb + 16384u + ldst[i], qkvl + rb + 2*Eq + i*8);
        CP_COMMIT();
    }

    const int arow = w*16 + (lane & 15);
    const uint32_t aRow = (uint32_t)arow * 128u;
    const uint32_t aMask = (uint32_t)(arow & 7) << 4;
    const uint32_t kA = ((uint32_t)(lane >> 4)) << 4;
    uint32_t bRow[4], bMask[4];
    #pragma unroll
    for (int p = 0; p < 4; p++) {
        int r = p*16 + (((lane >> 4) & 1) << 3) + (lane & 7);
        bRow[p]  = (uint32_t)r * 128u;
        bMask[p] = (uint32_t)(r & 7) << 4;
    }
    const uint32_t kB = ((uint32_t)(lane & 8)) << 1;
    const int vsub = lane >> 3, vrow = lane & 7;
    const int vtok = ((vsub & 1) << 3) + vrow;
    const int vd   = (vsub >> 1) << 3;

    float o[8][4];
    #pragma unroll
    for (int nf = 0; nf < 8; nf++)
        #pragma unroll
        for (int e = 0; e < 4; e++) o[nf][e] = 0.f;
    float m0r = -1e30f, m1r = -1e30f, l0r = 0.f, l1r = 0.f;

    const int nkt = qt + 1;
    for (int kt = 0; kt < nkt; kt++) {
        CP_WAIT0();
        __syncthreads();
        if (kt + 1 < nkt) {
            size_t rb = ((size_t)(bb*Tq + (kt+1)*64 + lr))*E3 + coloff;
            uint32_t kvb = sb + 16384u + (uint32_t)((kt+1) & 1)*24576u;
            #pragma unroll
            for (int i = 0; i < 4; i++) CP16(kvb + ldst[i],          qkvh + rb + Eq   + i*8);
            #pragma unroll
            for (int i = 0; i < 4; i++) CP16(kvb + 8192u + ldst[i],  qkvh + rb + 2*Eq + i*8);
            #pragma unroll
            for (int i = 0; i < 4; i++) CP16(kvb + 16384u + ldst[i], qkvl + rb + 2*Eq + i*8);
            CP_COMMIT();
        }
        const uint32_t kvb = sb + 16384u + (uint32_t)(kt & 1)*24576u;
        const uint32_t sK = kvb, sVh = kvb + 8192u, sVl = kvb + 16384u;

        float s[8][4];
        #pragma unroll
        for (int nf = 0; nf < 8; nf++)
            #pragma unroll
            for (int e = 0; e < 4; e++) s[nf][e] = 0.f;
        #pragma unroll
        for (int ks = 0; ks < 4; ks++) {
            uint32_t co = (uint32_t)(ks*32);
            uint32_t aoff = aRow + ((co + kA) ^ aMask);
            uint32_t ahr[4], alr[4];
            LDSM4(ahr[0], ahr[1], ahr[2], ahr[3], sQh + aoff);
            LDSM4(alr[0], alr[1], alr[2], alr[3], sQl + aoff);
            uint32_t bk[8][2];
            #pragma unroll
            for (int p = 0; p < 4; p++) {
                uint32_t off = bRow[p] + ((co + kB) ^ bMask[p]);
                uint32_t t0,t1,t2,t3;
                LDSM4(t0, t1, t2, t3, sK + off);
                bk[2*p][0]=t0; bk[2*p][1]=t1; bk[2*p+1][0]=t2; bk[2*p+1][1]=t3;
            }
            #pragma unroll
            for (int nf = 0; nf < 8; nf++)
                MMA_F16(s[nf], ahr, bk[nf]);
            #pragma unroll
            for (int nf = 0; nf < 8; nf++)
                MMA_F16(s[nf], alr, bk[nf]);
        }
        #pragma unroll
        for (int nf = 0; nf < 8; nf++)
            #pragma unroll
            for (int e = 0; e < 4; e++) s[nf][e] *= 0.125f;
        if (kt == qt) {
            int r0l = w*16 + (lane >> 2);
            #pragma unroll
            for (int nf = 0; nf < 8; nf++) {
                int col = nf*8 + ((lane & 3) << 1);
                if (col     > r0l)     s[nf][0] = -1e30f;
                if (col + 1 > r0l)     s[nf][1] = -1e30f;
                if (col     > r0l + 8) s[nf][2] = -1e30f;
                if (col + 1 > r0l + 8) s[nf][3] = -1e30f;
            }
        }
        float mx0 = -1e30f, mx1 = -1e30f;
        #pragma unroll
        for (int nf = 0; nf < 8; nf++) {
            mx0 = fmaxf(mx0, fmaxf(s[nf][0], s[nf][1]));
            mx1 = fmaxf(mx1, fmaxf(s[nf][2], s[nf][3]));
        }
        mx0 = fmaxf(mx0, __shfl_xor_sync(0xffffffffu, mx0, 1));
        mx0 = fmaxf(mx0, __shfl_xor_sync(0xffffffffu, mx0, 2));
        mx1 = fmaxf(mx1, __shfl_xor_sync(0xffffffffu, mx1, 1));
        mx1 = fmaxf(mx1, __shfl_xor_sync(0xffffffffu, mx1, 2));
        float mn0 = fmaxf(m0r, mx0), mn1 = fmaxf(m1r, mx1);
        float f0 = __expf(m0r - mn0), f1 = __expf(m1r - mn1);
        m0r = mn0; m1r = mn1;
        float ps0 = 0.f, ps1 = 0.f;
        #pragma unroll
        for (int nf = 0; nf < 8; nf++) {
            s[nf][0] = __expf(s[nf][0] - mn0); ps0 += s[nf][0];
            s[nf][1] = __expf(s[nf][1] - mn0); ps0 += s[nf][1];
            s[nf][2] = __expf(s[nf][2] - mn1); ps1 += s[nf][2];
            s[nf][3] = __expf(s[nf][3] - mn1); ps1 += s[nf][3];
        }
        ps0 += __shfl_xor_sync(0xffffffffu, ps0, 1);
        ps0 += __shfl_xor_sync(0xffffffffu, ps0, 2);
        ps1 += __shfl_xor_sync(0xffffffffu, ps1, 1);
        ps1 += __shfl_xor_sync(0xffffffffu, ps1, 2);
        l0r = l0r*f0 + ps0;
        l1r = l1r*f1 + ps1;
        #pragma unroll
        for (int nf = 0; nf < 8; nf++) {
            o[nf][0] *= f0; o[nf][1] *= f0;
            o[nf][2] *= f1; o[nf][3] *= f1;
        }
        #pragma unroll
        for (int kf = 0; kf < 4; kf++) {
            uint32_t ph[4], pl[4];
            split2h(s[2*kf][0],   s[2*kf][1],   ph[0], pl[0]);
            split2h(s[2*kf][2],   s[2*kf][3],   ph[1], pl[1]);
            split2h(s[2*kf+1][0], s[2*kf+1][1], ph[2], pl[2]);
            split2h(s[2*kf+1][2], s[2*kf+1][3], ph[3], pl[3]);
            int tok = kf*16 + vtok;
            uint32_t vrowoff = (uint32_t)tok * 128u;
            uint32_t vmask   = (uint32_t)(tok & 7) << 4;
            #pragma unroll
            for (int dw = 0; dw < 4; dw++) {
                uint32_t voff = vrowoff + (((uint32_t)((dw*16 + vd)*2)) ^ vmask);
                uint32_t h0,h1,h2,h3, g0,g1,g2,g3;
                LDSM4T(h0, h1, h2, h3, sVh + voff);
                LDSM4T(g0, g1, g2, g3, sVl + voff);
                MMA_F16B(o[2*dw],   ph, h0, h1);
                MMA_F16B(o[2*dw],   pl, h0, h1);
                MMA_F16B(o[2*dw],   ph, g0, g1);
                MMA_F16B(o[2*dw+1], ph, h2, h3);
                MMA_F16B(o[2*dw+1], pl, h2, h3);
                MMA_F16B(o[2*dw+1], ph, g2, g3);
            }
        }
    }

    float inv0 = 1.f / l0r, inv1 = 1.f / l1r;
    int row0 = q0 + w*16 + (lane >> 2);
    size_t base0 = ((size_t)(bb*Tq + row0))*Eq + (size_t)hh*64 + ((lane & 3) << 1);
    size_t base1 = base0 + (size_t)8*Eq;
    #pragma unroll
    for (int nf = 0; nf < 8; nf++) {
        uint32_t hv, lv;
        split2h(o[nf][0]*inv0, o[nf][1]*inv0, hv, lv);
        *(uint32_t*)(yhi + base0 + nf*8) = hv;
        *(uint32_t*)(ylo + base0 + nf*8) = lv;
        split2h(o[nf][2]*inv1, o[nf][3]*inv1, hv, lv);
        *(uint32_t*)(yhi + base1 + nf*8) = hv;
        *(uint32_t*)(ylo + base1 + nf*8) = lv;
    }
}

// ---------------- host orchestration ----------------------------------------
extern "C" void kernel_launch(void* const* d_in, const int* in_sizes, int n_in,
                              void* d_out, int out_size)
{
    const int*   x      = (const int*)  d_in[0];
    const float* tok    = (const float*)d_in[2];
    const float* pos    = (const float*)d_in[3];
    const float* ln1g   = (const float*)d_in[4];
    const float* ln1b   = (const float*)d_in[5];
    const float* Wqp    = (const float*)d_in[6];
    const float* bqp    = (const float*)d_in[7];
    const float* Wkp    = (const float*)d_in[8];
    const float* bkp    = (const float*)d_in[9];
    const float* Wvp    = (const float*)d_in[10];
    const float* bvp    = (const float*)d_in[11];
    const float* Wpp    = (const float*)d_in[12];
    const float* bpp    = (const float*)d_in[13];
    const float* ln2g   = (const float*)d_in[14];
    const float* ln2b   = (const float*)d_in[15];
    const float* Wf1p   = (const float*)d_in[16];
    const float* bf1p   = (const float*)d_in[17];
    const float* Wf2p   = (const float*)d_in[18];
    const float* bf2p   = (const float*)d_in[19];
    const float* lnfg   = (const float*)d_in[20];
    const float* lnfb   = (const float*)d_in[21];
    const float* headw  = (const float*)d_in[22];

    float *h, *bqkv;
    cudaGetSymbolAddress((void**)&h, g_h);
    cudaGetSymbolAddress((void**)&bqkv, g_bqkv);

    __half *xnh,*xnl,*qkvh,*qkvl,*yh,*yl,*mlh;
    cudaGetSymbolAddress((void**)&xnh, g_xn_hi);
    cudaGetSymbolAddress((void**)&xnl, g_xn_lo);
    cudaGetSymbolAddress((void**)&qkvh, g_qkv_hi);
    cudaGetSymbolAddress((void**)&qkvl, g_qkv_lo);
    cudaGetSymbolAddress((void**)&yh,  g_y_hi);
    cudaGetSymbolAddress((void**)&yl,  g_y_lo);
    cudaGetSymbolAddress((void**)&mlh, g_ml_hi);

    __half *wqkv,*wp,*w1,*w2,*wh;
    cudaGetSymbolAddress((void**)&wqkv, g_wqkv);
    cudaGetSymbolAddress((void**)&wp, g_wp);
    cudaGetSymbolAddress((void**)&w1, g_w1);
    cudaGetSymbolAddress((void**)&w2, g_w2);
    cudaGetSymbolAddress((void**)&wh, g_wh);

    cudaFuncSetAttribute(gemm_hf, cudaFuncAttributeMaxDynamicSharedMemorySize, GT_SMEM);
    cudaFuncSetAttribute(attn_fused, cudaFuncAttributeMaxDynamicSharedMemorySize, FA_SMEM);

    convAll<<<147980, 256>>>(Wqp, Wkp, Wvp, Wpp, Wf1p, Wf2p, headw,
                             bqp, bkp, bvp, wqkv, wp, w1, w2, wh, bqkv);
    embed_kernel<<<Mq, 256>>>(x, tok, pos, h);

    dim3 gQKV(E3/128, Mq/128);    // (24, 32)
    dim3 gEE(Eq/128, Mq/128);     // (8, 32)
    dim3 gEF(Fq/128, Mq/128);     // (32, 32)
    dim3 gEV(Vq/128, Mq/128);     // (4, 32)

    for (int l = 0; l < Lq; l++) {
        const size_t oE = (size_t)l*Eq*Eq;
        const size_t oF = (size_t)l*Eq*Fq;

        ln_kernel<<<Mq, 256>>>(h, ln1g + l*Eq, ln1b + l*Eq, xnh, xnl);
        gemm_hf<<<gQKV, 256, GT_SMEM>>>(xnh, xnl, wqkv + (size_t)l*E3*Eq,
                                        bqkv + l*E3, nullptr,
                                        nullptr, qkvh, qkvl, Mq, E3, Eq, 0);

        attn_fused<<<Bq*Hq*8, 128, FA_SMEM>>>(qkvh, qkvl, yh, yl);

        gemm_hf<<<gEE, 256, GT_SMEM>>>(yh, yl, wp+oE, bpp + l*Eq, h,
                                       h, nullptr, nullptr, Mq, Eq, Eq, 0);

        ln_kernel<<<Mq, 256>>>(h, ln2g + l*Eq, ln2b + l*Eq, xnh, xnl);
        // f1: A hi-only (1-term), output hi-only
        gemm_hf<<<gEF, 256, GT_SMEM>>>(xnh, nullptr, w1+oF, bf1p + l*Fq, nullptr,
                                       nullptr, mlh, nullptr, Mq, Fq, Eq, 1);
        // f2: A hi-only (1-term)
        gemm_hf<<<gEE, 256, GT_SMEM>>>(mlh, nullptr, w2+oF, bf2p + l*Eq, h,
                                       h, nullptr, nullptr, Mq, Eq, Fq, 0);
    }

    ln_kernel<<<Mq, 256>>>(h, lnfg, lnfb, xnh, xnl);
    gemm_hf<<<gEV, 256, GT_SMEM>>>(xnh, xnl, wh, nullptr, nullptr,
                                   (float*)d_out, nullptr, nullptr, Mq, Vq, Eq, 0);
}